// round 3
// baseline (speedup 1.0000x reference)
#include <cuda_runtime.h>

#define NN 100000
#define NE 1600000
#define NG 1000

// ---------------- scratch (device globals; no allocation) ----------------
__device__ float  d_h[NN * 64];
__device__ float  d_p[NN * 64];
__device__ float  d_u[NN * 64];
__device__ float  d_agg[NN * 64];
__device__ float  d_gpool[NG * 64];
__device__ int    d_cnt[NN];
__device__ int    d_ptr[NN + 1];
__device__ int    d_cursor[NN];
__device__ int    d_srcS[NE];
__device__ int    d_eidS[NE];
__device__ int    d_bsum[128];
__device__ float  d_C[3 * 16 * 64];
__device__ float  d_cv[3 * 64];
__device__ double d_stats[3 * 256];   // per layer: msgSum64, msgSq64, updSum64, updSq64
__device__ float  d_msc[3 * 64], d_msh[3 * 64];
__device__ float  d_usc[3 * 64], d_ush[3 * 64];

// ---------------- setup ----------------
__global__ void k_zero() {
    int i = blockIdx.x * blockDim.x + threadIdx.x;
    if (i < NN) d_cnt[i] = 0;
    if (i < 3 * 256) d_stats[i] = 0.0;
    if (i < NG * 64) d_gpool[i] = 0.f;
}

__global__ void k_hist(const int* __restrict__ dst) {
    for (int i = blockIdx.x * blockDim.x + threadIdx.x; i < NE; i += gridDim.x * blockDim.x)
        atomicAdd(&d_cnt[dst[i]], 1);
}

__global__ void k_scan1() {
    __shared__ int ws[32];
    int t = threadIdx.x;
    int i = blockIdx.x * 1024 + t;
    int v = (i < NN) ? d_cnt[i] : 0;
    int x = v;
#pragma unroll
    for (int off = 1; off < 32; off <<= 1) {
        int y = __shfl_up_sync(0xffffffffu, x, off);
        if ((t & 31) >= off) x += y;
    }
    if ((t & 31) == 31) ws[t >> 5] = x;
    __syncthreads();
    if (t < 32) {
        int y = ws[t]; int z = y;
#pragma unroll
        for (int off = 1; off < 32; off <<= 1) {
            int w = __shfl_up_sync(0xffffffffu, z, off);
            if (t >= off) z += w;
        }
        ws[t] = z - y;
    }
    __syncthreads();
    int excl = x - v + ws[t >> 5];
    if (i < NN) d_ptr[i] = excl;
    if (t == 1023) d_bsum[blockIdx.x] = excl + v;
}

__global__ void k_scan2(int nb) {
    if (threadIdx.x == 0) {
        int run = 0;
        for (int i = 0; i < nb; i++) { int t = d_bsum[i]; d_bsum[i] = run; run += t; }
    }
}

__global__ void k_scan3() {
    int i = blockIdx.x * blockDim.x + threadIdx.x;
    if (i < NN) {
        int val = d_ptr[i] + d_bsum[i >> 10];
        d_ptr[i] = val;
        d_cursor[i] = val;
    }
    if (i == 0) d_ptr[NN] = NE;
}

__global__ void k_scatter(const int* __restrict__ src, const int* __restrict__ dst) {
    for (int i = blockIdx.x * blockDim.x + threadIdx.x; i < NE; i += gridDim.x * blockDim.x) {
        int pos = atomicAdd(&d_cursor[dst[i]], 1);
        d_srcS[pos] = src[i];
        d_eidS[pos] = i;
    }
}

// C_l = edge_W @ msg_W[l][64:96,:]; cv_l = edge_b @ msg_W[l][64:96,:] + msg_b[l]
__global__ void k_composite(const float* __restrict__ edge_W, const float* __restrict__ edge_b,
                            const float* __restrict__ msg_W, const float* __restrict__ msg_b) {
    int l = blockIdx.x, f = threadIdx.x;
    const float* Wm = msg_W + l * 96 * 64 + 64 * 64;
    for (int kk = 0; kk < 16; kk++) {
        float s = 0.f;
        for (int j = 0; j < 32; j++) s = fmaf(edge_W[kk * 32 + j], Wm[j * 64 + f], s);
        d_C[l * 1024 + kk * 64 + f] = s;
    }
    float cv = msg_b[l * 64 + f];
    for (int j = 0; j < 32; j++) cv = fmaf(edge_b[j], Wm[j * 64 + f], cv);
    d_cv[l * 64 + f] = cv;
}

// h0 = x @ node_W + node_b (warp per node, weights in regs)
__global__ __launch_bounds__(256) void k_embed(const float* __restrict__ x,
                                               const float* __restrict__ W,
                                               const float* __restrict__ b) {
    int lane = threadIdx.x & 31;
    float w0[32], w1[32];
#pragma unroll
    for (int k = 0; k < 32; k++) { w0[k] = W[k * 64 + lane]; w1[k] = W[k * 64 + lane + 32]; }
    float b0 = b[lane], b1 = b[lane + 32];
    int gw = (blockIdx.x * blockDim.x + threadIdx.x) >> 5;
    int nw = (gridDim.x * blockDim.x) >> 5;
    for (int n = gw; n < NN; n += nw) {
        float xv = x[n * 32 + lane];
        float a0 = b0, a1 = b1;
#pragma unroll
        for (int k = 0; k < 32; k++) {
            float bc = __shfl_sync(0xffffffffu, xv, k);
            a0 = fmaf(bc, w0[k], a0); a1 = fmaf(bc, w1[k], a1);
        }
        d_h[n * 64 + lane] = a0; d_h[n * 64 + lane + 32] = a1;
    }
}

// p = h @ msg_W[l][0:64,:] — 2-warp split-K per node, 4 nodes/block
__global__ __launch_bounds__(256) void k_p(const float* __restrict__ msg_W, int l) {
    const float* W = msg_W + l * 96 * 64;
    int lane = threadIdx.x & 31;
    int half = (threadIdx.x >> 5) & 1;
    int pib  = threadIdx.x >> 6;
    float w0[32], w1[32];
#pragma unroll
    for (int kk = 0; kk < 32; kk++) {
        int k = half * 32 + kk;
        w0[kk] = W[k * 64 + lane]; w1[kk] = W[k * 64 + lane + 32];
    }
    __shared__ float2 red[4][32];
    int stride = gridDim.x * 4;
    for (int nb = blockIdx.x * 4; nb < NN; nb += stride) {
        int n = nb + pib;
        bool act = (n < NN);
        float a0 = 0.f, a1 = 0.f;
        if (act) {
            float hv = d_h[n * 64 + half * 32 + lane];
#pragma unroll
            for (int kk = 0; kk < 32; kk++) {
                float bc = __shfl_sync(0xffffffffu, hv, kk);
                a0 = fmaf(bc, w0[kk], a0); a1 = fmaf(bc, w1[kk], a1);
            }
        }
        if (half == 1) red[pib][lane] = make_float2(a0, a1);
        __syncthreads();
        if (act && half == 0) {
            float2 o = red[pib][lane];
            d_p[n * 64 + lane]      = a0 + o.x;
            d_p[n * 64 + lane + 32] = a1 + o.y;
        }
        __syncthreads();
    }
}

// HOT: warp per dst node; m = relu(p[src] + attr[eid]@C + cv); raw agg + BN stats
__global__ __launch_bounds__(256) void k_edge(const float* __restrict__ attr, int l) {
    int lane = threadIdx.x & 31;
    const float* C = d_C + l * 1024;
    float cw0[16], cw1[16];
#pragma unroll
    for (int k = 0; k < 16; k++) { cw0[k] = C[k * 64 + lane]; cw1[k] = C[k * 64 + lane + 32]; }
    float cb0 = d_cv[l * 64 + lane], cb1 = d_cv[l * 64 + lane + 32];
    float s0 = 0.f, q0 = 0.f, s1 = 0.f, q1 = 0.f;
    int gw = (blockIdx.x * blockDim.x + threadIdx.x) >> 5;
    int nw = (gridDim.x * blockDim.x) >> 5;
    for (int n = gw; n < NN; n += nw) {
        int beg = __ldg(&d_ptr[n]), end = __ldg(&d_ptr[n + 1]);
        float a0 = 0.f, a1 = 0.f;
        for (int j = beg; j < end; j++) {
            int srcn = __ldg(&d_srcS[j]);
            int eid  = __ldg(&d_eidS[j]);
            const float* pr = d_p + srcn * 64;
            float pv0 = __ldg(&pr[lane]), pv1 = __ldg(&pr[lane + 32]);
            float av  = __ldg(&attr[eid * 16 + (lane & 15)]);
            float m0 = pv0 + cb0, m1 = pv1 + cb1;
#pragma unroll
            for (int k = 0; k < 16; k++) {
                float bc = __shfl_sync(0xffffffffu, av, k);
                m0 = fmaf(bc, cw0[k], m0); m1 = fmaf(bc, cw1[k], m1);
            }
            m0 = fmaxf(m0, 0.f); m1 = fmaxf(m1, 0.f);
            a0 += m0; a1 += m1;
            s0 += m0; q0 = fmaf(m0, m0, q0);
            s1 += m1; q1 = fmaf(m1, m1, q1);
        }
        d_agg[n * 64 + lane]      = a0;
        d_agg[n * 64 + lane + 32] = a1;
    }
    __shared__ float sS[64], sQ[64];
    int t = threadIdx.x;
    if (t < 64) { sS[t] = 0.f; sQ[t] = 0.f; }
    __syncthreads();
    atomicAdd(&sS[lane], s0);      atomicAdd(&sS[lane + 32], s1);
    atomicAdd(&sQ[lane], q0);      atomicAdd(&sQ[lane + 32], q1);
    __syncthreads();
    double* st = d_stats + l * 256;
    if (t < 64) { atomicAdd(&st[t], (double)sS[t]); atomicAdd(&st[64 + t], (double)sQ[t]); }
}

__global__ void k_finalize(int l, int which, const float* __restrict__ gamma,
                           const float* __restrict__ beta, float invC) {
    int f = threadIdx.x;
    const double* st = d_stats + l * 256 + (which ? 128 : 0);
    double mu  = st[f] * (double)invC;
    double var = st[64 + f] * (double)invC - mu * mu;
    float sc = gamma[f] * rsqrtf((float)var + 1e-5f);
    float sh = beta[f] - (float)mu * sc;
    if (which == 0) { d_msc[l * 64 + f] = sc; d_msh[l * 64 + f] = sh; }
    else            { d_usc[l * 64 + f] = sc; d_ush[l * 64 + f] = sh; }
}

// u = relu( h @ Wu_h + (msc*agg + deg*msh) @ Wu_a + b ); 4-warp split-K, 2 nodes/block
__global__ __launch_bounds__(256) void k_update(const float* __restrict__ upd_W,
                                                const float* __restrict__ upd_b, int l) {
    const float* W = upd_W + l * 128 * 64;
    int lane = threadIdx.x & 31;
    int sub  = (threadIdx.x >> 5) & 3;
    int slot = threadIdx.x >> 7;
    float w0[32], w1[32];
#pragma unroll
    for (int kk = 0; kk < 32; kk++) {
        int k = sub * 32 + kk;
        w0[kk] = W[k * 64 + lane]; w1[kk] = W[k * 64 + lane + 32];
    }
    float b0 = upd_b[l * 64 + lane], b1 = upd_b[l * 64 + lane + 32];
    int j = (sub & 1) * 32 + lane;
    float msj = d_msc[l * 64 + j], mshj = d_msh[l * 64 + j];
    __shared__ float2 red[2][4][32];
    float s0 = 0.f, q0 = 0.f, s1 = 0.f, q1 = 0.f;
    int stride = gridDim.x * 2;
    for (int nb = blockIdx.x * 2; nb < NN; nb += stride) {
        int n = nb + slot;
        bool act = (n < NN);
        float a0 = 0.f, a1 = 0.f;
        if (act) {
            float iv;
            if (sub < 2) iv = d_h[n * 64 + j];
            else {
                float degf = (float)(d_ptr[n + 1] - d_ptr[n]);
                iv = fmaf(msj, d_agg[n * 64 + j], degf * mshj);
            }
#pragma unroll
            for (int kk = 0; kk < 32; kk++) {
                float bc = __shfl_sync(0xffffffffu, iv, kk);
                a0 = fmaf(bc, w0[kk], a0); a1 = fmaf(bc, w1[kk], a1);
            }
        }
        if (sub) red[slot][sub][lane] = make_float2(a0, a1);
        __syncthreads();
        if (act && sub == 0) {
            float2 r1 = red[slot][1][lane], r2 = red[slot][2][lane], r3 = red[slot][3][lane];
            float v0 = a0 + r1.x + r2.x + r3.x + b0;
            float v1 = a1 + r1.y + r2.y + r3.y + b1;
            v0 = fmaxf(v0, 0.f); v1 = fmaxf(v1, 0.f);
            d_u[n * 64 + lane]      = v0;
            d_u[n * 64 + lane + 32] = v1;
            s0 += v0; q0 = fmaf(v0, v0, q0);
            s1 += v1; q1 = fmaf(v1, v1, q1);
        }
        __syncthreads();
    }
    __shared__ float sS[64], sQ[64];
    int t = threadIdx.x;
    if (t < 64) { sS[t] = 0.f; sQ[t] = 0.f; }
    __syncthreads();
    if (sub == 0) {
        atomicAdd(&sS[lane], s0);      atomicAdd(&sS[lane + 32], s1);
        atomicAdd(&sQ[lane], q0);      atomicAdd(&sQ[lane + 32], q1);
    }
    __syncthreads();
    double* st = d_stats + l * 256 + 128;
    if (t < 64) { atomicAdd(&st[t], (double)sS[t]); atomicAdd(&st[64 + t], (double)sQ[t]); }
}

// h = usc*u + ush  (vectorized: 16 float4 per node row of 64)
__global__ void k_norm(int l) {
    int i = blockIdx.x * blockDim.x + threadIdx.x;
    if (i < NN * 16) {
        int f4 = (i & 15) * 4;
        const float4* up = (const float4*)d_u;
        float4* hp = (float4*)d_h;
        float4 u = up[i];
        float4 sc = *(const float4*)&d_usc[l * 64 + f4];
        float4 sh = *(const float4*)&d_ush[l * 64 + f4];
        float4 r;
        r.x = fmaf(sc.x, u.x, sh.x);
        r.y = fmaf(sc.y, u.y, sh.y);
        r.z = fmaf(sc.z, u.z, sh.z);
        r.w = fmaf(sc.w, u.w, sh.w);
        hp[i] = r;
    }
}

__global__ __launch_bounds__(256) void k_pool(const int* __restrict__ batch) {
    int lane = threadIdx.x & 31;
    int gw = (blockIdx.x * blockDim.x + threadIdx.x) >> 5;
    int nw = (gridDim.x * blockDim.x) >> 5;
    for (int n = gw; n < NN; n += nw) {
        int g = batch[n];
        atomicAdd(&d_gpool[g * 64 + lane],      d_h[n * 64 + lane]);
        atomicAdd(&d_gpool[g * 64 + lane + 32], d_h[n * 64 + lane + 32]);
    }
}

__global__ void k_readout(const float* __restrict__ r1_W, const float* __restrict__ r1_b,
                          const float* __restrict__ r2_W, const float* __restrict__ r2_b,
                          float* __restrict__ out) {
    int gid = blockIdx.x, f = threadIdx.x;
    float acc = r1_b[f];
    for (int k = 0; k < 64; k++)
        acc = fmaf(d_gpool[gid * 64 + k], r1_W[k * 64 + f], acc);
    acc = fmaxf(acc, 0.f);
    float val = acc * r2_W[f];
    __shared__ float sh[64];
    sh[f] = val;
    __syncthreads();
    if (f < 32) { sh[f] += sh[f + 32]; }
    __syncthreads();
    if (f < 16) sh[f] += sh[f + 16];
    __syncthreads();
    if (f < 8) sh[f] += sh[f + 8];
    __syncthreads();
    if (f < 4) sh[f] += sh[f + 4];
    __syncthreads();
    if (f < 2) sh[f] += sh[f + 2];
    __syncthreads();
    if (f == 0) out[gid] = sh[0] + sh[1] + r2_b[0];
}

extern "C" void kernel_launch(void* const* d_in, const int* in_sizes, int n_in,
                              void* d_out, int out_size) {
    const float* x         = (const float*)d_in[0];
    const float* edge_attr = (const float*)d_in[1];
    const int*   edge_idx  = (const int*)d_in[2];
    const int*   batch     = (const int*)d_in[3];
    const float* node_W    = (const float*)d_in[4];
    const float* node_b    = (const float*)d_in[5];
    const float* edge_W    = (const float*)d_in[6];
    const float* edge_b    = (const float*)d_in[7];
    const float* msg_W     = (const float*)d_in[8];
    const float* msg_b     = (const float*)d_in[9];
    const float* msg_gamma = (const float*)d_in[10];
    const float* msg_beta  = (const float*)d_in[11];
    const float* upd_W     = (const float*)d_in[12];
    const float* upd_b     = (const float*)d_in[13];
    const float* upd_gamma = (const float*)d_in[14];
    const float* upd_beta  = (const float*)d_in[15];
    const float* r1_W      = (const float*)d_in[16];
    const float* r1_b      = (const float*)d_in[17];
    const float* r2_W      = (const float*)d_in[18];
    const float* r2_b      = (const float*)d_in[19];
    float* out = (float*)d_out;

    const int* src = edge_idx;
    const int* dst = edge_idx + NE;

    k_zero<<<(NN + 255) / 256, 256>>>();
    k_hist<<<1024, 256>>>(dst);
    int nb = (NN + 1023) / 1024;
    k_scan1<<<nb, 1024>>>();
    k_scan2<<<1, 32>>>(nb);
    k_scan3<<<(NN + 255) / 256, 256>>>();
    k_scatter<<<1024, 256>>>(src, dst);
    k_composite<<<3, 64>>>(edge_W, edge_b, msg_W, msg_b);
    k_embed<<<512, 256>>>(x, node_W, node_b);

    for (int l = 0; l < 3; l++) {
        k_p<<<1024, 256>>>(msg_W, l);
        k_edge<<<2048, 256>>>(edge_attr, l);
        k_finalize<<<1, 64>>>(l, 0, msg_gamma + l * 64, msg_beta + l * 64, 1.0f / NE);
        k_update<<<1024, 256>>>(upd_W, upd_b, l);
        k_finalize<<<1, 64>>>(l, 1, upd_gamma + l * 64, upd_beta + l * 64, 1.0f / NN);
        k_norm<<<(NN * 16 + 255) / 256, 256>>>(l);
    }
    k_pool<<<2048, 256>>>(batch);
    k_readout<<<NG, 64>>>(r1_W, r1_b, r2_W, r2_b, out);
}